// round 12
// baseline (speedup 1.0000x reference)
#include <cuda_runtime.h>
#include <cuda_fp16.h>
#include <cstdint>
#include <math.h>

#define BATCH 8
#define SEQ   2048
#define DIM   1024
#define BN_ROWS (BATCH * SEQ)     // 16384

// ---------------- tile config ----------------
// CTA tile 128x128, 128 threads (4 warps, 2x2 grid), warp tile 64x64.
#define TMt 128
#define TNt 128
#define TKt 64                     // fp16 elems per k-chunk (128B rows, SW128)

static constexpr int OFF_A = 0;
static constexpr int OFF_B = 16384;
static constexpr int STAGE_BYTES = 32768;
static constexpr int NSTAGE = 3;
static constexpr int SMEM_TOTAL = NSTAGE * STAGE_BYTES;  // 98304 -> 2 CTAs/SM

// ---------------- scratch (__device__ globals; no allocs allowed) --------------
__device__ __half g_x16[(long long)BN_ROWS * DIM];       // x fp16
__device__ __half g_wt16[3u * DIM * DIM];                // W^T fp16 (q,k,v)
__device__ __half g_q16[(long long)BN_ROWS * DIM];       // Q fp16
__device__ __half g_k16[(long long)BN_ROWS * DIM];       // K fp16
__device__ __half g_vt16[(long long)BATCH * DIM * SEQ];  // V^T fp16 [b][dim][seq]
__device__ __half g_p16[(long long)BATCH * SEQ * SEQ];   // P = exp(s/32), fp16 (unnormalized)
__device__ float  g_rowsum[BN_ROWS];                     // per-q-row sum of exp

// ---------------- PTX helpers ----------------
__device__ __forceinline__ uint32_t smem_u32(const void* p) {
    uint32_t a;
    asm("{ .reg .u64 t; cvta.to.shared.u64 t, %1; cvt.u32.u64 %0, t; }" : "=r"(a) : "l"(p));
    return a;
}
__device__ __forceinline__ void cp16(uint32_t saddr, const void* g) {
    asm volatile("cp.async.cg.shared.global [%0], [%1], 16;" :: "r"(saddr), "l"(g));
}
#define CP_COMMIT() asm volatile("cp.async.commit_group;" ::: "memory")
#define CP_WAIT1()  asm volatile("cp.async.wait_group 1;" ::: "memory")
#define CP_WAIT0()  asm volatile("cp.async.wait_group 0;" ::: "memory")

__device__ __forceinline__ void ldsm_x4(uint32_t (&r)[4], uint32_t addr) {
    asm volatile("ldmatrix.sync.aligned.m8n8.x4.shared.b16 {%0,%1,%2,%3}, [%4];"
        : "=r"(r[0]), "=r"(r[1]), "=r"(r[2]), "=r"(r[3]) : "r"(addr));
}
__device__ __forceinline__ void mma_f16(float (&d)[4], const uint32_t (&a)[4],
                                        uint32_t b0, uint32_t b1) {
    asm volatile("mma.sync.aligned.m16n8k16.row.col.f32.f16.f16.f32 "
        "{%0,%1,%2,%3}, {%4,%5,%6,%7}, {%8,%9}, {%0,%1,%2,%3};"
        : "+f"(d[0]), "+f"(d[1]), "+f"(d[2]), "+f"(d[3])
        : "r"(a[0]), "r"(a[1]), "r"(a[2]), "r"(a[3]), "r"(b0), "r"(b1));
}
__device__ __forceinline__ uint32_t sw128(uint32_t off) {
    return off ^ (((off >> 7) & 7) << 4);
}

// ==================== fp16 single-product GEMM (64x64 warp tiles) ====================
// C[M,N] = A[M,K] @ B[N,K]^T, fp32 accumulate, both operands fp16.
// MODE 0: fused QKV. z: 0 -> Q (+biasQ), 1 -> K (+biasK), 2 -> V (+biasV, transposed)
// MODE 1: final PV: fp32 out scaled by 1/rowsum[m]
// MODE 2: scores: store exp(s/32) as fp16 P + atomic row-sums of exp
template <int MODE>
__global__ __launch_bounds__(128, 2)
void gemm_fp16(const __half* __restrict__ A, int lda,
               const __half* __restrict__ B, int ldb,
               const float* __restrict__ biasQ, const float* __restrict__ biasK, const float* __restrict__ biasV,
               float* __restrict__ Fo, float* __restrict__ Rsum,
               __half* __restrict__ Oq, __half* __restrict__ Ok, __half* __restrict__ Ov,
               int ldo, int K, long long sA, long long sB, long long sO)
{
    extern __shared__ __align__(1024) char smem[];
    const uint32_t smb = smem_u32(smem);
    const int tid  = threadIdx.x;
    const int lane = tid & 31;
    const int wid  = tid >> 5;
    const int wm   = wid & 1;          // 2 warps along M
    const int wn   = wid >> 1;         // 2 warps along N
    const int z = blockIdx.z;
    const int rowBase = blockIdx.y * TMt;
    const int colBase = blockIdx.x * TNt;

    const __half* Ap = A + sA * z + (long long)rowBase * lda;
    const __half* Bp = B + sB * z + (long long)colBase * ldb;

    auto load_stage = [&](int st, int kt) {
        const int k0 = kt * TKt;
        const uint32_t sb = smb + st * STAGE_BYTES;
#pragma unroll
        for (int i = 0; i < 8; i++) {
            const int c  = tid + i * 128;      // 0..1023
            const int r  = c >> 3;
            const int cc = c & 7;
            const uint32_t sw = sw128((uint32_t)(r * 128 + cc * 16));
            cp16(sb + OFF_A + sw, Ap + (long long)r * lda + k0 + cc * 8);
            cp16(sb + OFF_B + sw, Bp + (long long)r * ldb + k0 + cc * 8);
        }
        CP_COMMIT();
    };

    float acc[4][8][4];
#pragma unroll
    for (int a = 0; a < 4; a++)
#pragma unroll
        for (int b = 0; b < 8; b++)
#pragma unroll
            for (int c = 0; c < 4; c++) acc[a][b][c] = 0.f;

    const int nk = K / TKt;
    load_stage(0, 0);
    load_stage(1, 1);

    for (int t = 0; t < nk; t++) {
        if (t + 1 < nk) { CP_WAIT1(); } else { CP_WAIT0(); }
        __syncthreads();
        if (t + 2 < nk) load_stage((t + 2) % NSTAGE, t + 2);

        const uint32_t sb = smb + (t % NSTAGE) * STAGE_BYTES;
#pragma unroll
        for (int kk = 0; kk < TKt; kk += 16) {
            uint32_t af[4][4], bf[4][4];
#pragma unroll
            for (int mt = 0; mt < 4; mt++) {
                const int r = wm * 64 + mt * 16 + (lane & 15);
                const uint32_t sw = sw128((uint32_t)(r * 128 + kk * 2 + ((lane >> 4) << 4)));
                ldsm_x4(af[mt], sb + OFF_A + sw);
            }
#pragma unroll
            for (int np = 0; np < 4; np++) {
                const int r = wn * 64 + np * 16 + (lane & 7) + ((lane >> 4) << 3);
                const uint32_t sw = sw128((uint32_t)(r * 128 + kk * 2 + (((lane >> 3) & 1) << 4)));
                ldsm_x4(bf[np], sb + OFF_B + sw);
            }
#pragma unroll
            for (int mt = 0; mt < 4; mt++)
#pragma unroll
                for (int np = 0; np < 4; np++) {
                    mma_f16(acc[mt][np * 2 + 0], af[mt], bf[np][0], bf[np][1]);
                    mma_f16(acc[mt][np * 2 + 1], af[mt], bf[np][2], bf[np][3]);
                }
        }
    }

    // ---------------- epilogue ----------------
    const int mB = wm * 64;
    const int nB = wn * 64;

    if (MODE == 1) {
        // final PV: scale each row by 1/rowsum (deferred softmax normalization)
#pragma unroll
        for (int mt = 0; mt < 4; mt++)
#pragma unroll
            for (int h = 0; h < 2; h++) {
                const int m = rowBase + mB + mt * 16 + (lane >> 2) + h * 8;
                const float inv = 1.0f / __ldg(&Rsum[z * SEQ + m]);
#pragma unroll
                for (int nt = 0; nt < 8; nt++) {
                    const int n = colBase + nB + nt * 8 + ((lane & 3) << 1);
                    float2 fv;
                    fv.x = acc[mt][nt][h * 2 + 0] * inv;
                    fv.y = acc[mt][nt][h * 2 + 1] * inv;
                    *(float2*)(Fo + sO * z + (long long)m * ldo + n) = fv;
                }
            }
    } else if (MODE == 2) {
        // scores: e = exp(s/32) stored fp16, row-sums accumulated atomically
        const float scale = 0.03125f;
#pragma unroll
        for (int mt = 0; mt < 4; mt++)
#pragma unroll
            for (int h = 0; h < 2; h++) {
                const int m = rowBase + mB + mt * 16 + (lane >> 2) + h * 8;
                float part = 0.f;
#pragma unroll
                for (int nt = 0; nt < 8; nt++) {
                    const int n = colBase + nB + nt * 8 + ((lane & 3) << 1);
                    const float e0 = __expf(acc[mt][nt][h * 2 + 0] * scale);
                    const float e1 = __expf(acc[mt][nt][h * 2 + 1] * scale);
                    part += e0 + e1;
                    __half2 hv;
                    hv.x = __float2half_rn(e0);
                    hv.y = __float2half_rn(e1);
                    *(__half2*)(Oq + sO * z + (long long)m * ldo + n) = hv;
                }
                part += __shfl_xor_sync(0xffffffffu, part, 1);
                part += __shfl_xor_sync(0xffffffffu, part, 2);
                if ((lane & 3) == 0)
                    atomicAdd(&Rsum[z * SEQ + m], part);
            }
    } else if (z != 2) {
        // Q or K: fp16 row-major (+bias)
        const float* bias = (z == 0) ? biasQ : biasK;
        __half* O = (z == 0) ? Oq : Ok;
#pragma unroll
        for (int mt = 0; mt < 4; mt++)
#pragma unroll
            for (int nt = 0; nt < 8; nt++)
#pragma unroll
                for (int h = 0; h < 2; h++) {
                    const int m = rowBase + mB + mt * 16 + (lane >> 2) + h * 8;
                    const int n = colBase + nB + nt * 8 + ((lane & 3) << 1);
                    __half2 hv;
                    hv.x = __float2half_rn(acc[mt][nt][h * 2 + 0] + __ldg(&bias[n]));
                    hv.y = __float2half_rn(acc[mt][nt][h * 2 + 1] + __ldg(&bias[n + 1]));
                    *(__half2*)(O + (long long)m * DIM + n) = hv;
                }
    } else {
        // V: fp16, transposed per batch via smem bounce
        __half* Th = (__half*)smem;     // [128 n][136 m]
        __syncthreads();
#pragma unroll
        for (int mt = 0; mt < 4; mt++)
#pragma unroll
            for (int nt = 0; nt < 8; nt++)
#pragma unroll
                for (int h = 0; h < 2; h++) {
                    const int ml = mB + mt * 16 + (lane >> 2) + h * 8;
                    const int nl = nB + nt * 8 + ((lane & 3) << 1);
#pragma unroll
                    for (int j = 0; j < 2; j++) {
                        float v = acc[mt][nt][h * 2 + j] + __ldg(&biasV[colBase + nl + j]);
                        Th[(nl + j) * 136 + ml] = __float2half_rn(v);
                    }
                }
        __syncthreads();
        const int b   = rowBase >> 11;
        const int pos = rowBase & (SEQ - 1);
        const long long bb = (long long)b * DIM * SEQ + pos;
        for (int c = tid; c < 128 * 16; c += 128) {
            const int nr = c >> 4;
            const int cc = c & 15;
            const long long go = bb + (long long)(colBase + nr) * SEQ + cc * 8;
            *(uint4*)(Ov + go) = *(uint4*)(Th + nr * 136 + cc * 8);
        }
    }
}

// ---------------- prep kernels ----------------
// fp32 -> fp16 convert (float4 vectorized)
__global__ void cvt_kernel(const float* __restrict__ src, __half* __restrict__ dst, long long n4)
{
    const long long stride = (long long)gridDim.x * blockDim.x;
    for (long long i = (long long)blockIdx.x * blockDim.x + threadIdx.x; i < n4; i += stride) {
        const float4 a = ((const float4*)src)[i];
        __half2 h0, h1;
        h0.x = __float2half_rn(a.x);
        h0.y = __float2half_rn(a.y);
        h1.x = __float2half_rn(a.z);
        h1.y = __float2half_rn(a.w);
        ((__half2*)dst)[i * 2 + 0] = h0;
        ((__half2*)dst)[i * 2 + 1] = h1;
    }
}

// batched transpose: z selects which W; Wt[n][k] = W[k][n], fp32 -> fp16
__global__ void wtrans_kernel(const float* __restrict__ W0, const float* __restrict__ W1,
                              const float* __restrict__ W2, __half* __restrict__ T16)
{
    const int z = blockIdx.z;
    const float* W = (z == 0) ? W0 : (z == 1) ? W1 : W2;
    __half* T = T16 + (long long)z * DIM * DIM;

    __shared__ float t[32][33];
    const int x = blockIdx.x * 32 + threadIdx.x;
    const int y0 = blockIdx.y * 32;
#pragma unroll
    for (int i = 0; i < 32; i += 8)
        t[threadIdx.y + i][threadIdx.x] = W[(long long)(y0 + threadIdx.y + i) * DIM + x];
    __syncthreads();
#pragma unroll
    for (int i = 0; i < 32; i += 8) {
        const float val = t[threadIdx.x][threadIdx.y + i];
        const int n = blockIdx.x * 32 + threadIdx.y + i;
        const int k = y0 + threadIdx.x;
        T[(long long)n * DIM + k] = __float2half_rn(val);
    }
}

// ---------------- launch ----------------
extern "C" void kernel_launch(void* const* d_in, const int* in_sizes, int n_in,
                              void* d_out, int out_size)
{
    const float* x  = (const float*)d_in[0];
    const float* Wq = (const float*)d_in[1];
    const float* bq = (const float*)d_in[2];
    const float* Wk = (const float*)d_in[3];
    const float* bk = (const float*)d_in[4];
    const float* Wv = (const float*)d_in[5];
    const float* bv = (const float*)d_in[6];
    float* out = (float*)d_out;

    __half *x16, *wt16, *q16, *k16, *vt16, *p16;
    float* rsum;
    cudaGetSymbolAddress((void**)&x16,  g_x16);
    cudaGetSymbolAddress((void**)&wt16, g_wt16);
    cudaGetSymbolAddress((void**)&q16,  g_q16);
    cudaGetSymbolAddress((void**)&k16,  g_k16);
    cudaGetSymbolAddress((void**)&vt16, g_vt16);
    cudaGetSymbolAddress((void**)&p16,  g_p16);
    cudaGetSymbolAddress((void**)&rsum, g_rowsum);

    cudaFuncSetAttribute(gemm_fp16<0>, cudaFuncAttributeMaxDynamicSharedMemorySize, SMEM_TOTAL);
    cudaFuncSetAttribute(gemm_fp16<1>, cudaFuncAttributeMaxDynamicSharedMemorySize, SMEM_TOTAL);
    cudaFuncSetAttribute(gemm_fp16<2>, cudaFuncAttributeMaxDynamicSharedMemorySize, SMEM_TOTAL);

    // zero row-sum accumulators (graph-capturable async memset)
    cudaMemsetAsync(rsum, 0, BN_ROWS * sizeof(float));

    // prep: convert x -> fp16 (float4), batched transpose W -> fp16
    cvt_kernel<<<2048, 256>>>(x, x16, (long long)BN_ROWS * DIM / 4);
    {
        dim3 g(DIM / 32, DIM / 32, 3), b(32, 8);
        wtrans_kernel<<<g, b>>>(Wq, Wk, Wv, wt16);
    }

    const dim3 blk(128);
    const long long sQK = (long long)SEQ * DIM;
    const long long sSS = (long long)SEQ * SEQ;

    // fused QKV projections
    {
        dim3 g(DIM / TNt, BN_ROWS / TMt, 3);   // (8, 128, 3)
        gemm_fp16<0><<<g, blk, SMEM_TOTAL>>>(x16, DIM, wt16, DIM,
                                             bq, bk, bv, nullptr, nullptr,
                                             q16, k16, vt16,
                                             DIM, DIM, 0, (long long)DIM * DIM, 0);
    }
    // scores: P = exp(QK^T/32) fp16 + row sums (softmax fused, normalization deferred)
    {
        dim3 g(SEQ / TNt, SEQ / TMt, BATCH);   // (16, 16, 8)
        gemm_fp16<2><<<g, blk, SMEM_TOTAL>>>(q16, DIM, k16, DIM,
                                             nullptr, nullptr, nullptr, nullptr, rsum,
                                             p16, nullptr, nullptr,
                                             SEQ, DIM, sQK, sQK, sSS);
    }
    // out = (P @ V) / rowsum   (V^T, K=SEQ, fp32 out)
    {
        dim3 g(DIM / TNt, SEQ / TMt, BATCH);   // (8, 16, 8)
        gemm_fp16<1><<<g, blk, SMEM_TOTAL>>>(p16, SEQ, vt16, SEQ,
                                             nullptr, nullptr, nullptr, out, rsum,
                                             nullptr, nullptr, nullptr,
                                             DIM, SEQ, sSS, (long long)DIM * SEQ, sQK);
    }
}

// round 14
// speedup vs baseline: 1.0461x; 1.0461x over previous
#include <cuda_runtime.h>
#include <cuda_fp16.h>
#include <cstdint>
#include <math.h>

#define BATCH 8
#define SEQ   2048
#define DIM   1024
#define BN_ROWS (BATCH * SEQ)     // 16384

// ---------------- tile config ----------------
#define TMt 128
#define TNt 128
#define TKt 64                     // fp16 elems per k-chunk (128B rows, SW128)

static constexpr int OFF_A = 0;
static constexpr int OFF_B = 16384;
static constexpr int STAGE_BYTES = 32768;
static constexpr int NSTAGE = 3;
static constexpr int SMEM_TOTAL = NSTAGE * STAGE_BYTES;  // 98304 -> 2 CTAs/SM

// ---------------- scratch (__device__ globals; no allocs allowed) --------------
__device__ __half g_x16[(long long)BN_ROWS * DIM];       // x fp16
__device__ __half g_wt16[3u * DIM * DIM];                // W^T fp16 (q,k,v)
__device__ __half g_q16[(long long)BN_ROWS * DIM];       // Q fp16
__device__ __half g_k16[(long long)BN_ROWS * DIM];       // K fp16
__device__ __half g_vt16[(long long)BATCH * DIM * SEQ];  // V^T fp16 [b][dim][seq]
__device__ __half g_p16[(long long)BATCH * SEQ * SEQ];   // P = exp(s/32), fp16 (unnormalized)
__device__ float  g_rowsum[BN_ROWS];                     // per-q-row sum of exp

// ---------------- PTX helpers ----------------
__device__ __forceinline__ uint32_t smem_u32(const void* p) {
    uint32_t a;
    asm("{ .reg .u64 t; cvta.to.shared.u64 t, %1; cvt.u32.u64 %0, t; }" : "=r"(a) : "l"(p));
    return a;
}
__device__ __forceinline__ void cp16(uint32_t saddr, const void* g) {
    asm volatile("cp.async.cg.shared.global [%0], [%1], 16;" :: "r"(saddr), "l"(g));
}
#define CP_COMMIT() asm volatile("cp.async.commit_group;" ::: "memory")
#define CP_WAIT1()  asm volatile("cp.async.wait_group 1;" ::: "memory")
#define CP_WAIT0()  asm volatile("cp.async.wait_group 0;" ::: "memory")

__device__ __forceinline__ void ldsm_x4(uint32_t (&r)[4], uint32_t addr) {
    asm volatile("ldmatrix.sync.aligned.m8n8.x4.shared.b16 {%0,%1,%2,%3}, [%4];"
        : "=r"(r[0]), "=r"(r[1]), "=r"(r[2]), "=r"(r[3]) : "r"(addr));
}
__device__ __forceinline__ void mma_f16(float (&d)[4], const uint32_t (&a)[4],
                                        uint32_t b0, uint32_t b1) {
    asm volatile("mma.sync.aligned.m16n8k16.row.col.f32.f16.f16.f32 "
        "{%0,%1,%2,%3}, {%4,%5,%6,%7}, {%8,%9}, {%0,%1,%2,%3};"
        : "+f"(d[0]), "+f"(d[1]), "+f"(d[2]), "+f"(d[3])
        : "r"(a[0]), "r"(a[1]), "r"(a[2]), "r"(a[3]), "r"(b0), "r"(b1));
}
__device__ __forceinline__ uint32_t sw128(uint32_t off) {
    return off ^ (((off >> 7) & 7) << 4);
}

// ==================== fp16 single-product GEMM (round-11 winning config) ====================
// C[M,N] = A[M,K] @ B[N,K]^T, fp32 accumulate, both operands fp16.
// 256 threads, 4x2 warp grid, 32x64 warp tile, 3-stage cp.async, 2 CTAs/SM.
// MODE 0: fused QKV. z: 0 -> Q (+biasQ), 1 -> K (+biasK), 2 -> V (+biasV, transposed)
// MODE 1: final PV: fp32 out scaled by 1/rowsum[m]
// MODE 2: scores: store exp(s/32) as fp16 P + atomic row-sums of exp
template <int MODE>
__global__ __launch_bounds__(256, 2)
void gemm_fp16(const __half* __restrict__ A, int lda,
               const __half* __restrict__ B, int ldb,
               const float* __restrict__ biasQ, const float* __restrict__ biasK, const float* __restrict__ biasV,
               float* __restrict__ Fo, float* __restrict__ Rsum,
               __half* __restrict__ Oq, __half* __restrict__ Ok, __half* __restrict__ Ov,
               int ldo, int K, long long sA, long long sB, long long sO)
{
    extern __shared__ __align__(1024) char smem[];
    const uint32_t smb = smem_u32(smem);
    const int tid  = threadIdx.x;
    const int lane = tid & 31;
    const int wid  = tid >> 5;
    const int wm   = wid & 3;          // 4 warps along M
    const int wn   = wid >> 2;         // 2 warps along N
    const int z = blockIdx.z;
    const int rowBase = blockIdx.y * TMt;
    const int colBase = blockIdx.x * TNt;

    const __half* Ap = A + sA * z + (long long)rowBase * lda;
    const __half* Bp = B + sB * z + (long long)colBase * ldb;

    auto load_stage = [&](int st, int kt) {
        const int k0 = kt * TKt;
        const uint32_t sb = smb + st * STAGE_BYTES;
#pragma unroll
        for (int i = 0; i < 4; i++) {
            const int c  = tid + i * 256;      // 0..1023
            const int r  = c >> 3;
            const int cc = c & 7;
            const uint32_t sw = sw128((uint32_t)(r * 128 + cc * 16));
            cp16(sb + OFF_A + sw, Ap + (long long)r * lda + k0 + cc * 8);
            cp16(sb + OFF_B + sw, Bp + (long long)r * ldb + k0 + cc * 8);
        }
        CP_COMMIT();
    };

    float acc[2][8][4];
#pragma unroll
    for (int a = 0; a < 2; a++)
#pragma unroll
        for (int b = 0; b < 8; b++)
#pragma unroll
            for (int c = 0; c < 4; c++) acc[a][b][c] = 0.f;

    const int nk = K / TKt;
    load_stage(0, 0);
    load_stage(1, 1);

    for (int t = 0; t < nk; t++) {
        if (t + 1 < nk) { CP_WAIT1(); } else { CP_WAIT0(); }
        __syncthreads();
        if (t + 2 < nk) load_stage((t + 2) % NSTAGE, t + 2);

        const uint32_t sb = smb + (t % NSTAGE) * STAGE_BYTES;
#pragma unroll
        for (int kk = 0; kk < TKt; kk += 16) {
            uint32_t af[2][4], bf[4][4];
#pragma unroll
            for (int mt = 0; mt < 2; mt++) {
                const int r = wm * 32 + mt * 16 + (lane & 15);
                const uint32_t sw = sw128((uint32_t)(r * 128 + kk * 2 + ((lane >> 4) << 4)));
                ldsm_x4(af[mt], sb + OFF_A + sw);
            }
#pragma unroll
            for (int np = 0; np < 4; np++) {
                const int r = wn * 64 + np * 16 + (lane & 7) + ((lane >> 4) << 3);
                const uint32_t sw = sw128((uint32_t)(r * 128 + kk * 2 + (((lane >> 3) & 1) << 4)));
                ldsm_x4(bf[np], sb + OFF_B + sw);
            }
#pragma unroll
            for (int mt = 0; mt < 2; mt++)
#pragma unroll
                for (int np = 0; np < 4; np++) {
                    mma_f16(acc[mt][np * 2 + 0], af[mt], bf[np][0], bf[np][1]);
                    mma_f16(acc[mt][np * 2 + 1], af[mt], bf[np][2], bf[np][3]);
                }
        }
    }

    // ---------------- epilogue ----------------
    const int mB = wm * 32;
    const int nB = wn * 64;

    if (MODE == 1) {
        // final PV: scale each row by 1/rowsum (deferred softmax normalization)
        float inv[2][2];
#pragma unroll
        for (int mt = 0; mt < 2; mt++)
#pragma unroll
            for (int h = 0; h < 2; h++) {
                const int m = rowBase + mB + mt * 16 + (lane >> 2) + h * 8;
                inv[mt][h] = 1.0f / __ldg(&Rsum[z * SEQ + m]);
            }
#pragma unroll
        for (int mt = 0; mt < 2; mt++)
#pragma unroll
            for (int h = 0; h < 2; h++) {
                const int m = rowBase + mB + mt * 16 + (lane >> 2) + h * 8;
#pragma unroll
                for (int nt = 0; nt < 8; nt++) {
                    const int n = colBase + nB + nt * 8 + ((lane & 3) << 1);
                    float2 fv;
                    fv.x = acc[mt][nt][h * 2 + 0] * inv[mt][h];
                    fv.y = acc[mt][nt][h * 2 + 1] * inv[mt][h];
                    *(float2*)(Fo + sO * z + (long long)m * ldo + n) = fv;
                }
            }
    } else if (MODE == 2) {
        // scores: e = exp(s/32) stored fp16, row-sums accumulated atomically
        const float scale = 0.03125f;
#pragma unroll
        for (int mt = 0; mt < 2; mt++)
#pragma unroll
            for (int h = 0; h < 2; h++) {
                const int m = rowBase + mB + mt * 16 + (lane >> 2) + h * 8;
                float part = 0.f;
#pragma unroll
                for (int nt = 0; nt < 8; nt++) {
                    const int n = colBase + nB + nt * 8 + ((lane & 3) << 1);
                    const float e0 = __expf(acc[mt][nt][h * 2 + 0] * scale);
                    const float e1 = __expf(acc[mt][nt][h * 2 + 1] * scale);
                    part += e0 + e1;
                    __half2 hv;
                    hv.x = __float2half_rn(e0);
                    hv.y = __float2half_rn(e1);
                    *(__half2*)(Oq + sO * z + (long long)m * ldo + n) = hv;
                }
                part += __shfl_xor_sync(0xffffffffu, part, 1);
                part += __shfl_xor_sync(0xffffffffu, part, 2);
                if ((lane & 3) == 0)
                    atomicAdd(&Rsum[z * SEQ + m], part);
            }
    } else if (z != 2) {
        // Q or K: fp16 row-major (+bias)
        const float* bias = (z == 0) ? biasQ : biasK;
        __half* O = (z == 0) ? Oq : Ok;
#pragma unroll
        for (int mt = 0; mt < 2; mt++)
#pragma unroll
            for (int nt = 0; nt < 8; nt++)
#pragma unroll
                for (int h = 0; h < 2; h++) {
                    const int m = rowBase + mB + mt * 16 + (lane >> 2) + h * 8;
                    const int n = colBase + nB + nt * 8 + ((lane & 3) << 1);
                    __half2 hv;
                    hv.x = __float2half_rn(acc[mt][nt][h * 2 + 0] + __ldg(&bias[n]));
                    hv.y = __float2half_rn(acc[mt][nt][h * 2 + 1] + __ldg(&bias[n + 1]));
                    *(__half2*)(O + (long long)m * DIM + n) = hv;
                }
    } else {
        // V: fp16, transposed per batch via smem bounce
        __half* Th = (__half*)smem;     // [128 n][136 m]
        __syncthreads();
#pragma unroll
        for (int mt = 0; mt < 2; mt++)
#pragma unroll
            for (int nt = 0; nt < 8; nt++)
#pragma unroll
                for (int h = 0; h < 2; h++) {
                    const int ml = mB + mt * 16 + (lane >> 2) + h * 8;
                    const int nl = nB + nt * 8 + ((lane & 3) << 1);
#pragma unroll
                    for (int j = 0; j < 2; j++) {
                        float v = acc[mt][nt][h * 2 + j] + __ldg(&biasV[colBase + nl + j]);
                        Th[(nl + j) * 136 + ml] = __float2half_rn(v);
                    }
                }
        __syncthreads();
        const int b   = rowBase >> 11;
        const int pos = rowBase & (SEQ - 1);
        const long long bb = (long long)b * DIM * SEQ + pos;
        for (int c = tid; c < 128 * 16; c += 256) {
            const int nr = c >> 4;
            const int cc = c & 15;
            const long long go = bb + (long long)(colBase + nr) * SEQ + cc * 8;
            *(uint4*)(Ov + go) = *(uint4*)(Th + nr * 136 + cc * 8);
        }
    }
}

// ---------------- fused prep kernel ----------------
// Launched on grid (32, 32, 4) x 256 threads.
// z = 0: convert x fp32 -> fp16 (grid-stride over all of x)
// z = 1..3: transpose W_{q,k,v} fp32 -> fp16 (exactly 32x32 blocks of 32x32 tiles)
__global__ void prep_kernel(const float* __restrict__ x, __half* __restrict__ x16,
                            const float* __restrict__ W0, const float* __restrict__ W1,
                            const float* __restrict__ W2, __half* __restrict__ T16)
{
    const int z = blockIdx.z;
    if (z == 0) {
        const long long n4 = (long long)BN_ROWS * DIM / 4;   // 4194304
        const long long stride = 32LL * 32 * 256;            // 262144
        for (long long i = ((long long)blockIdx.y * 32 + blockIdx.x) * 256 + threadIdx.x;
             i < n4; i += stride) {
            const float4 a = ((const float4*)x)[i];
            __half2 h0, h1;
            h0.x = __float2half_rn(a.x);
            h0.y = __float2half_rn(a.y);
            h1.x = __float2half_rn(a.z);
            h1.y = __float2half_rn(a.w);
            ((__half2*)x16)[i * 2 + 0] = h0;
            ((__half2*)x16)[i * 2 + 1] = h1;
        }
    } else {
        const float* W = (z == 1) ? W0 : (z == 2) ? W1 : W2;
        __half* T = T16 + (long long)(z - 1) * DIM * DIM;
        __shared__ float t[32][33];
        const int tx = threadIdx.x & 31;
        const int ty = threadIdx.x >> 5;   // 0..7
        const int xg = blockIdx.x * 32 + tx;       // 0..1023
        const int y0 = blockIdx.y * 32;            // 0..992
#pragma unroll
        for (int i = 0; i < 32; i += 8)
            t[ty + i][tx] = W[(long long)(y0 + ty + i) * DIM + xg];
        __syncthreads();
#pragma unroll
        for (int i = 0; i < 32; i += 8) {
            const float val = t[tx][ty + i];
            const int n = blockIdx.x * 32 + ty + i;
            const int k = y0 + tx;
            T[(long long)n * DIM + k] = __float2half_rn(val);
        }
    }
}

// ---------------- launch ----------------
extern "C" void kernel_launch(void* const* d_in, const int* in_sizes, int n_in,
                              void* d_out, int out_size)
{
    const float* x  = (const float*)d_in[0];
    const float* Wq = (const float*)d_in[1];
    const float* bq = (const float*)d_in[2];
    const float* Wk = (const float*)d_in[3];
    const float* bk = (const float*)d_in[4];
    const float* Wv = (const float*)d_in[5];
    const float* bv = (const float*)d_in[6];
    float* out = (float*)d_out;

    __half *x16, *wt16, *q16, *k16, *vt16, *p16;
    float* rsum;
    cudaGetSymbolAddress((void**)&x16,  g_x16);
    cudaGetSymbolAddress((void**)&wt16, g_wt16);
    cudaGetSymbolAddress((void**)&q16,  g_q16);
    cudaGetSymbolAddress((void**)&k16,  g_k16);
    cudaGetSymbolAddress((void**)&vt16, g_vt16);
    cudaGetSymbolAddress((void**)&p16,  g_p16);
    cudaGetSymbolAddress((void**)&rsum, g_rowsum);

    cudaFuncSetAttribute(gemm_fp16<0>, cudaFuncAttributeMaxDynamicSharedMemorySize, SMEM_TOTAL);
    cudaFuncSetAttribute(gemm_fp16<1>, cudaFuncAttributeMaxDynamicSharedMemorySize, SMEM_TOTAL);
    cudaFuncSetAttribute(gemm_fp16<2>, cudaFuncAttributeMaxDynamicSharedMemorySize, SMEM_TOTAL);

    // zero row-sum accumulators (graph-capturable async memset)
    cudaMemsetAsync(rsum, 0, BN_ROWS * sizeof(float));

    // fused prep: x convert + 3x W transpose in one launch (grid y fixed to 32!)
    {
        dim3 g(32, 32, 4), b(256);
        prep_kernel<<<g, b>>>(x, x16, Wq, Wk, Wv, wt16);
    }

    const dim3 blk(256);
    const long long sQK = (long long)SEQ * DIM;
    const long long sSS = (long long)SEQ * SEQ;

    // fused QKV projections
    {
        dim3 g(DIM / TNt, BN_ROWS / TMt, 3);   // (8, 128, 3)
        gemm_fp16<0><<<g, blk, SMEM_TOTAL>>>(x16, DIM, wt16, DIM,
                                             bq, bk, bv, nullptr, nullptr,
                                             q16, k16, vt16,
                                             DIM, DIM, 0, (long long)DIM * DIM, 0);
    }
    // scores: P = exp(QK^T/32) fp16 + row sums (softmax fused, normalization deferred)
    {
        dim3 g(SEQ / TNt, SEQ / TMt, BATCH);   // (16, 16, 8)
        gemm_fp16<2><<<g, blk, SMEM_TOTAL>>>(q16, DIM, k16, DIM,
                                             nullptr, nullptr, nullptr, nullptr, rsum,
                                             p16, nullptr, nullptr,
                                             SEQ, DIM, sQK, sQK, sSS);
    }
    // out = (P @ V) / rowsum   (V^T, K=SEQ, fp32 out)
    {
        dim3 g(DIM / TNt, SEQ / TMt, BATCH);   // (8, 16, 8)
        gemm_fp16<1><<<g, blk, SMEM_TOTAL>>>(p16, SEQ, vt16, SEQ,
                                             nullptr, nullptr, nullptr, out, rsum,
                                             nullptr, nullptr, nullptr,
                                             DIM, SEQ, sSS, (long long)DIM * SEQ, sQK);
    }
}

// round 15
// speedup vs baseline: 1.0521x; 1.0057x over previous
#include <cuda_runtime.h>
#include <cuda_fp16.h>
#include <cstdint>
#include <math.h>

#define BATCH 8
#define SEQ   2048
#define DIM   1024
#define BN_ROWS (BATCH * SEQ)     // 16384

// ---------------- tile config ----------------
#define TMt 128
#define TNt 128
#define TKt 64                     // fp16 elems per k-chunk (128B rows, SW128)

static constexpr int OFF_A = 0;
static constexpr int OFF_B = 16384;
static constexpr int STAGE_BYTES = 32768;
static constexpr int NSTAGE = 3;
static constexpr int SMEM_TOTAL = NSTAGE * STAGE_BYTES;  // 98304 -> 2 CTAs/SM

// ---------------- scratch (__device__ globals; no allocs allowed) --------------
__device__ __half g_x16[(long long)BN_ROWS * DIM];       // x fp16
__device__ __half g_wt16[3u * DIM * DIM];                // W^T fp16 (q,k,v)
__device__ __half g_q16[(long long)BN_ROWS * DIM];       // Q fp16
__device__ __half g_k16[(long long)BN_ROWS * DIM];       // K fp16
__device__ __half g_vt16[(long long)BATCH * DIM * SEQ];  // V^T fp16 [b][dim][seq]
__device__ __half g_p16[(long long)BATCH * SEQ * SEQ];   // P = exp(s/32), fp16 (unnormalized)
__device__ float  g_rowsum[BN_ROWS];                     // per-q-row sum of exp

// ---------------- PTX helpers ----------------
__device__ __forceinline__ uint32_t smem_u32(const void* p) {
    uint32_t a;
    asm("{ .reg .u64 t; cvta.to.shared.u64 t, %1; cvt.u32.u64 %0, t; }" : "=r"(a) : "l"(p));
    return a;
}
__device__ __forceinline__ void cp16(uint32_t saddr, const void* g) {
    asm volatile("cp.async.cg.shared.global [%0], [%1], 16;" :: "r"(saddr), "l"(g));
}
#define CP_COMMIT() asm volatile("cp.async.commit_group;" ::: "memory")
#define CP_WAIT1()  asm volatile("cp.async.wait_group 1;" ::: "memory")
#define CP_WAIT0()  asm volatile("cp.async.wait_group 0;" ::: "memory")

__device__ __forceinline__ void ldsm_x4(uint32_t (&r)[4], uint32_t addr) {
    asm volatile("ldmatrix.sync.aligned.m8n8.x4.shared.b16 {%0,%1,%2,%3}, [%4];"
        : "=r"(r[0]), "=r"(r[1]), "=r"(r[2]), "=r"(r[3]) : "r"(addr));
}
__device__ __forceinline__ void mma_f16(float (&d)[4], const uint32_t (&a)[4],
                                        uint32_t b0, uint32_t b1) {
    asm volatile("mma.sync.aligned.m16n8k16.row.col.f32.f16.f16.f32 "
        "{%0,%1,%2,%3}, {%4,%5,%6,%7}, {%8,%9}, {%0,%1,%2,%3};"
        : "+f"(d[0]), "+f"(d[1]), "+f"(d[2]), "+f"(d[3])
        : "r"(a[0]), "r"(a[1]), "r"(a[2]), "r"(a[3]), "r"(b0), "r"(b1));
}
__device__ __forceinline__ uint32_t sw128(uint32_t off) {
    return off ^ (((off >> 7) & 7) << 4);
}

// ==================== fp16 single-product GEMM (winning config) ====================
// C[M,N] = A[M,K] @ B[N,K]^T, fp32 accumulate, both operands fp16.
// 256 threads, 4x2 warp grid, 32x64 warp tile, 3-stage cp.async, 2 CTAs/SM.
// MODE 0: fused QKV. z: 0 -> Q (+biasQ), 1 -> K (+biasK), 2 -> V (+biasV, transposed)
// MODE 1: final PV: fp32 out scaled by 1/rowsum[m]
// MODE 2: scores: store exp(s/32) as fp16 P + atomic row-sums of exp
template <int MODE>
__global__ __launch_bounds__(256, 2)
void gemm_fp16(const __half* __restrict__ A, int lda,
               const __half* __restrict__ B, int ldb,
               const float* __restrict__ biasQ, const float* __restrict__ biasK, const float* __restrict__ biasV,
               float* __restrict__ Fo, float* __restrict__ Rsum,
               __half* __restrict__ Oq, __half* __restrict__ Ok, __half* __restrict__ Ov,
               int ldo, int K, long long sA, long long sB, long long sO)
{
    extern __shared__ __align__(1024) char smem[];
    const uint32_t smb = smem_u32(smem);
    const int tid  = threadIdx.x;
    const int lane = tid & 31;
    const int wid  = tid >> 5;
    const int wm   = wid & 3;          // 4 warps along M
    const int wn   = wid >> 2;         // 2 warps along N
    const int z = blockIdx.z;
    const int rowBase = blockIdx.y * TMt;
    const int colBase = blockIdx.x * TNt;

    const __half* Ap = A + sA * z + (long long)rowBase * lda;
    const __half* Bp = B + sB * z + (long long)colBase * ldb;

    auto load_stage = [&](int st, int kt) {
        const int k0 = kt * TKt;
        const uint32_t sb = smb + st * STAGE_BYTES;
#pragma unroll
        for (int i = 0; i < 4; i++) {
            const int c  = tid + i * 256;      // 0..1023
            const int r  = c >> 3;
            const int cc = c & 7;
            const uint32_t sw = sw128((uint32_t)(r * 128 + cc * 16));
            cp16(sb + OFF_A + sw, Ap + (long long)r * lda + k0 + cc * 8);
            cp16(sb + OFF_B + sw, Bp + (long long)r * ldb + k0 + cc * 8);
        }
        CP_COMMIT();
    };

    float acc[2][8][4];
#pragma unroll
    for (int a = 0; a < 2; a++)
#pragma unroll
        for (int b = 0; b < 8; b++)
#pragma unroll
            for (int c = 0; c < 4; c++) acc[a][b][c] = 0.f;

    const int nk = K / TKt;
    load_stage(0, 0);
    load_stage(1, 1);

    for (int t = 0; t < nk; t++) {
        if (t + 1 < nk) { CP_WAIT1(); } else { CP_WAIT0(); }
        __syncthreads();
        if (t + 2 < nk) load_stage((t + 2) % NSTAGE, t + 2);

        const uint32_t sb = smb + (t % NSTAGE) * STAGE_BYTES;
#pragma unroll
        for (int kk = 0; kk < TKt; kk += 16) {
            uint32_t af[2][4], bf[4][4];
#pragma unroll
            for (int mt = 0; mt < 2; mt++) {
                const int r = wm * 32 + mt * 16 + (lane & 15);
                const uint32_t sw = sw128((uint32_t)(r * 128 + kk * 2 + ((lane >> 4) << 4)));
                ldsm_x4(af[mt], sb + OFF_A + sw);
            }
#pragma unroll
            for (int np = 0; np < 4; np++) {
                const int r = wn * 64 + np * 16 + (lane & 7) + ((lane >> 4) << 3);
                const uint32_t sw = sw128((uint32_t)(r * 128 + kk * 2 + (((lane >> 3) & 1) << 4)));
                ldsm_x4(bf[np], sb + OFF_B + sw);
            }
#pragma unroll
            for (int mt = 0; mt < 2; mt++)
#pragma unroll
                for (int np = 0; np < 4; np++) {
                    mma_f16(acc[mt][np * 2 + 0], af[mt], bf[np][0], bf[np][1]);
                    mma_f16(acc[mt][np * 2 + 1], af[mt], bf[np][2], bf[np][3]);
                }
        }
    }

    // ---------------- epilogue ----------------
    const int mB = wm * 32;
    const int nB = wn * 64;

    if (MODE == 1) {
        // final PV: scale each row by 1/rowsum (deferred softmax normalization)
        float inv[2][2];
#pragma unroll
        for (int mt = 0; mt < 2; mt++)
#pragma unroll
            for (int h = 0; h < 2; h++) {
                const int m = rowBase + mB + mt * 16 + (lane >> 2) + h * 8;
                inv[mt][h] = 1.0f / __ldg(&Rsum[z * SEQ + m]);
            }
#pragma unroll
        for (int mt = 0; mt < 2; mt++)
#pragma unroll
            for (int h = 0; h < 2; h++) {
                const int m = rowBase + mB + mt * 16 + (lane >> 2) + h * 8;
#pragma unroll
                for (int nt = 0; nt < 8; nt++) {
                    const int n = colBase + nB + nt * 8 + ((lane & 3) << 1);
                    float2 fv;
                    fv.x = acc[mt][nt][h * 2 + 0] * inv[mt][h];
                    fv.y = acc[mt][nt][h * 2 + 1] * inv[mt][h];
                    *(float2*)(Fo + sO * z + (long long)m * ldo + n) = fv;
                }
            }
    } else if (MODE == 2) {
        // scores: e = exp(s/32) stored fp16, row-sums accumulated atomically
        const float scale = 0.03125f;
#pragma unroll
        for (int mt = 0; mt < 2; mt++)
#pragma unroll
            for (int h = 0; h < 2; h++) {
                const int m = rowBase + mB + mt * 16 + (lane >> 2) + h * 8;
                float part = 0.f;
#pragma unroll
                for (int nt = 0; nt < 8; nt++) {
                    const int n = colBase + nB + nt * 8 + ((lane & 3) << 1);
                    const float e0 = __expf(acc[mt][nt][h * 2 + 0] * scale);
                    const float e1 = __expf(acc[mt][nt][h * 2 + 1] * scale);
                    part += e0 + e1;
                    __half2 hv;
                    hv.x = __float2half_rn(e0);
                    hv.y = __float2half_rn(e1);
                    *(__half2*)(Oq + sO * z + (long long)m * ldo + n) = hv;
                }
                part += __shfl_xor_sync(0xffffffffu, part, 1);
                part += __shfl_xor_sync(0xffffffffu, part, 2);
                if ((lane & 3) == 0)
                    atomicAdd(&Rsum[z * SEQ + m], part);
            }
    } else if (z != 2) {
        // Q or K: fp16 row-major (+bias)
        const float* bias = (z == 0) ? biasQ : biasK;
        __half* O = (z == 0) ? Oq : Ok;
#pragma unroll
        for (int mt = 0; mt < 2; mt++)
#pragma unroll
            for (int nt = 0; nt < 8; nt++)
#pragma unroll
                for (int h = 0; h < 2; h++) {
                    const int m = rowBase + mB + mt * 16 + (lane >> 2) + h * 8;
                    const int n = colBase + nB + nt * 8 + ((lane & 3) << 1);
                    __half2 hv;
                    hv.x = __float2half_rn(acc[mt][nt][h * 2 + 0] + __ldg(&bias[n]));
                    hv.y = __float2half_rn(acc[mt][nt][h * 2 + 1] + __ldg(&bias[n + 1]));
                    *(__half2*)(O + (long long)m * DIM + n) = hv;
                }
    } else {
        // V: fp16, transposed per batch via smem bounce
        __half* Th = (__half*)smem;     // [128 n][136 m]
        __syncthreads();
#pragma unroll
        for (int mt = 0; mt < 2; mt++)
#pragma unroll
            for (int nt = 0; nt < 8; nt++)
#pragma unroll
                for (int h = 0; h < 2; h++) {
                    const int ml = mB + mt * 16 + (lane >> 2) + h * 8;
                    const int nl = nB + nt * 8 + ((lane & 3) << 1);
#pragma unroll
                    for (int j = 0; j < 2; j++) {
                        float v = acc[mt][nt][h * 2 + j] + __ldg(&biasV[colBase + nl + j]);
                        Th[(nl + j) * 136 + ml] = __float2half_rn(v);
                    }
                }
        __syncthreads();
        const int b   = rowBase >> 11;
        const int pos = rowBase & (SEQ - 1);
        const long long bb = (long long)b * DIM * SEQ + pos;
        for (int c = tid; c < 128 * 16; c += 256) {
            const int nr = c >> 4;
            const int cc = c & 15;
            const long long go = bb + (long long)(colBase + nr) * SEQ + cc * 8;
            *(uint4*)(Ov + go) = *(uint4*)(Th + nr * 136 + cc * 8);
        }
    }
}

// ---------------- fused prep kernel ----------------
// Launched on grid (32, 32, 4) x 256 threads.
// z = 0: zero rsum (first 16384 threads) + convert x fp32 -> fp16 (grid-stride)
// z = 1..3: transpose W_{q,k,v} fp32 -> fp16 (exactly 32x32 blocks of 32x32 tiles)
__global__ void prep_kernel(const float* __restrict__ x, __half* __restrict__ x16,
                            const float* __restrict__ W0, const float* __restrict__ W1,
                            const float* __restrict__ W2, __half* __restrict__ T16,
                            float* __restrict__ rsum)
{
    const int z = blockIdx.z;
    if (z == 0) {
        const long long gid0 = ((long long)blockIdx.y * 32 + blockIdx.x) * 256 + threadIdx.x;
        if (gid0 < BN_ROWS) rsum[gid0] = 0.f;   // fold memset into prep

        const long long n4 = (long long)BN_ROWS * DIM / 4;   // 4194304
        const long long stride = 32LL * 32 * 256;            // 262144
        for (long long i = gid0; i < n4; i += stride) {
            const float4 a = ((const float4*)x)[i];
            __half2 h0, h1;
            h0.x = __float2half_rn(a.x);
            h0.y = __float2half_rn(a.y);
            h1.x = __float2half_rn(a.z);
            h1.y = __float2half_rn(a.w);
            ((__half2*)x16)[i * 2 + 0] = h0;
            ((__half2*)x16)[i * 2 + 1] = h1;
        }
    } else {
        const float* W = (z == 1) ? W0 : (z == 2) ? W1 : W2;
        __half* T = T16 + (long long)(z - 1) * DIM * DIM;
        __shared__ float t[32][33];
        const int tx = threadIdx.x & 31;
        const int ty = threadIdx.x >> 5;   // 0..7
        const int xg = blockIdx.x * 32 + tx;       // 0..1023
        const int y0 = blockIdx.y * 32;            // 0..992
#pragma unroll
        for (int i = 0; i < 32; i += 8)
            t[ty + i][tx] = W[(long long)(y0 + ty + i) * DIM + xg];
        __syncthreads();
#pragma unroll
        for (int i = 0; i < 32; i += 8) {
            const float val = t[tx][ty + i];
            const int n = blockIdx.x * 32 + ty + i;
            const int k = y0 + tx;
            T[(long long)n * DIM + k] = __float2half_rn(val);
        }
    }
}

// ---------------- launch ----------------
extern "C" void kernel_launch(void* const* d_in, const int* in_sizes, int n_in,
                              void* d_out, int out_size)
{
    const float* x  = (const float*)d_in[0];
    const float* Wq = (const float*)d_in[1];
    const float* bq = (const float*)d_in[2];
    const float* Wk = (const float*)d_in[3];
    const float* bk = (const float*)d_in[4];
    const float* Wv = (const float*)d_in[5];
    const float* bv = (const float*)d_in[6];
    float* out = (float*)d_out;

    __half *x16, *wt16, *q16, *k16, *vt16, *p16;
    float* rsum;
    cudaGetSymbolAddress((void**)&x16,  g_x16);
    cudaGetSymbolAddress((void**)&wt16, g_wt16);
    cudaGetSymbolAddress((void**)&q16,  g_q16);
    cudaGetSymbolAddress((void**)&k16,  g_k16);
    cudaGetSymbolAddress((void**)&vt16, g_vt16);
    cudaGetSymbolAddress((void**)&p16,  g_p16);
    cudaGetSymbolAddress((void**)&rsum, g_rowsum);

    cudaFuncSetAttribute(gemm_fp16<0>, cudaFuncAttributeMaxDynamicSharedMemorySize, SMEM_TOTAL);
    cudaFuncSetAttribute(gemm_fp16<1>, cudaFuncAttributeMaxDynamicSharedMemorySize, SMEM_TOTAL);
    cudaFuncSetAttribute(gemm_fp16<2>, cudaFuncAttributeMaxDynamicSharedMemorySize, SMEM_TOTAL);

    // fused prep: rsum zero + x convert + 3x W transpose in one launch
    {
        dim3 g(32, 32, 4), b(256);
        prep_kernel<<<g, b>>>(x, x16, Wq, Wk, Wv, wt16, rsum);
    }

    const dim3 blk(256);
    const long long sQK = (long long)SEQ * DIM;
    const long long sSS = (long long)SEQ * SEQ;

    // fused QKV projections
    {
        dim3 g(DIM / TNt, BN_ROWS / TMt, 3);   // (8, 128, 3)
        gemm_fp16<0><<<g, blk, SMEM_TOTAL>>>(x16, DIM, wt16, DIM,
                                             bq, bk, bv, nullptr, nullptr,
                                             q16, k16, vt16,
                                             DIM, DIM, 0, (long long)DIM * DIM, 0);
    }
    // scores: P = exp(QK^T/32) fp16 + row sums (softmax fused, normalization deferred)
    {
        dim3 g(SEQ / TNt, SEQ / TMt, BATCH);   // (16, 16, 8)
        gemm_fp16<2><<<g, blk, SMEM_TOTAL>>>(q16, DIM, k16, DIM,
                                             nullptr, nullptr, nullptr, nullptr, rsum,
                                             p16, nullptr, nullptr,
                                             SEQ, DIM, sQK, sQK, sSS);
    }
    // out = (P @ V) / rowsum   (V^T, K=SEQ, fp32 out)
    {
        dim3 g(DIM / TNt, SEQ / TMt, BATCH);   // (8, 16, 8)
        gemm_fp16<1><<<g, blk, SMEM_TOTAL>>>(p16, SEQ, vt16, SEQ,
                                             nullptr, nullptr, nullptr, out, rsum,
                                             nullptr, nullptr, nullptr,
                                             DIM, SEQ, sSS, (long long)DIM * SEQ, sQK);
    }
}